// round 17
// baseline (speedup 1.0000x reference)
#include <cuda_runtime.h>
#include <cuda_fp16.h>
#include <cstdint>
#include <cstddef>

#define BB   32
#define PS   1536
#define TNS  2048
#define NJ   128
#define QK   384
#define NC   200
#define NCT  12          // c-tiles per batch in GEMM1

// ---------------------------------------------------------------------------
// scratch (static device globals; no allocation)
// ---------------------------------------------------------------------------
__device__ __half g_w0h [(size_t)NJ * TNS];       // w0 rounded fp16
__device__ __half g_h1  [(size_t)BB * NJ * PS];   // hs1^T [b][j][c], fp16
__device__ float g_qp  [(size_t)BB * NCT * NJ];
__device__ float g_kp  [(size_t)BB * NCT * NJ];
__device__ float g_sbc [(size_t)BB * PS];
__device__ float g_ssbc[(size_t)BB * PS];
__device__ float g_dotb[(size_t)BB * PS];
__device__ float g_wqm[PS];
__device__ float g_wkm[PS];
__device__ float g_bqkm[2];
__device__ float g_hs4[BB * PS];

// ---------------------------------------------------------------------------
// helpers
// ---------------------------------------------------------------------------
__device__ __forceinline__ uint32_t smem_u32(const void* p) {
    uint32_t a;
    asm("{ .reg .u64 t; cvta.to.shared.u64 t, %1; cvt.u32.u64 %0, t; }" : "=r"(a) : "l"(p));
    return a;
}
#define CP_COMMIT() asm volatile("cp.async.commit_group;" ::: "memory")
#define CP_WAIT0()  asm volatile("cp.async.wait_group 0;" ::: "memory")
#define CP_WAIT1()  asm volatile("cp.async.wait_group 1;" ::: "memory")

__device__ __forceinline__ void ld4(uint32_t* r, uint32_t a) {
    asm volatile("ldmatrix.sync.aligned.m8n8.x4.shared.b16 {%0,%1,%2,%3}, [%4];"
        : "=r"(r[0]), "=r"(r[1]), "=r"(r[2]), "=r"(r[3]) : "r"(a));
}
__device__ __forceinline__ void mma16816(float* d, const uint32_t* a, const uint32_t* b) {
    asm volatile(
        "mma.sync.aligned.m16n8k16.row.col.f32.f16.f16.f32 "
        "{%0,%1,%2,%3}, {%4,%5,%6,%7}, {%8,%9}, {%0,%1,%2,%3};"
        : "+f"(d[0]), "+f"(d[1]), "+f"(d[2]), "+f"(d[3])
        : "r"(a[0]), "r"(a[1]), "r"(a[2]), "r"(a[3]), "r"(b[0]), "r"(b[1]));
}

// combined prep: blocks [0,256): w0 fp32->fp16 round; [256,304): wq/wk column
// means; 304/305: bias means.
__global__ void k_prep(const float* __restrict__ w0,
                       const float* __restrict__ wq, const float* __restrict__ wk,
                       const float* __restrict__ bq, const float* __restrict__ bk) {
    const int bx = blockIdx.x;
    if (bx < 256) {
        long i = (long)bx * 256 + threadIdx.x;    // < NJ*TNS/4 = 65536
        float4 v = ((const float4*)w0)[i];
        __half2 h01 = __floats2half2_rn(v.x, v.y);
        __half2 h23 = __floats2half2_rn(v.z, v.w);
        ((__half2*)g_w0h)[i * 2 + 0] = h01;
        ((__half2*)g_w0h)[i * 2 + 1] = h23;
    } else if (bx < 304) {
        const int tx = threadIdx.x & 31, ty = threadIdx.x >> 5;
        const int c = (bx - 256) * 32 + tx;
        float sq = 0.f, sk = 0.f;
        for (int o = ty; o < QK; o += 8) {
            sq += wq[(size_t)o * PS + c];
            sk += wk[(size_t)o * PS + c];
        }
        __shared__ float aq[8][32], ak[8][32];
        aq[ty][tx] = sq; ak[ty][tx] = sk;
        __syncthreads();
        if (ty == 0) {
#pragma unroll
            for (int u = 1; u < 8; u++) { sq += aq[u][tx]; sk += ak[u][tx]; }
            g_wqm[c] = sq * (1.0f / QK);
            g_wkm[c] = sk * (1.0f / QK);
        }
    } else if (threadIdx.x < 32) {
        const float* src = (bx == 304) ? bq : bk;
        float s = 0.f;
        for (int o = threadIdx.x; o < QK; o += 32) s += src[o];
#pragma unroll
        for (int o = 16; o > 0; o >>= 1) s += __shfl_down_sync(0xffffffffu, s, o);
        if (threadIdx.x == 0) g_bqkm[bx - 304] = s * (1.0f / QK);
    }
}

// ---------------------------------------------------------------------------
// SMEM tile: 128 rows x 128 k fp16, 256B/row + 16 pad (272B == 4 banks mod 32)
// ---------------------------------------------------------------------------
#define BK    128
#define RSTR  272
#define TILEB (128 * RSTR)     // 34816
#define STG2  (2 * TILEB)

__device__ __forceinline__ void load_tile(uint32_t sb, const __half* g, int gstride, int k0) {
    const int t = threadIdx.x;
#pragma unroll
    for (int p = 0; p < 8; p++) {
        int idx = p * 256 + t;
        int row = idx >> 4, ch = idx & 15;
        uint32_t dst = sb + row * RSTR + ch * 16;
        const void* src = g + (size_t)row * gstride + k0 + ch * 8;
        asm volatile("cp.async.cg.shared.global [%0], [%1], 16;" :: "r"(dst), "l"(src));
    }
}

// 1-term MMA over one stage (8 k16 steps): tile0 = A, tile1 = B
#define MMA_STAGE_1T(st)                                                         \
    do {                                                                         \
        _Pragma("unroll")                                                        \
        for (int ks = 0; ks < 8; ks++) {                                         \
            const uint32_t klo = ks * 32;                                        \
            uint32_t ah[4][4], bf[2][4];                                         \
            _Pragma("unroll")                                                    \
            for (int mt = 0; mt < 4; mt++) ld4(ah[mt], (st) + 0 * TILEB + aoff[mt] + klo); \
            _Pragma("unroll")                                                    \
            for (int np = 0; np < 2; np++) ld4(bf[np], (st) + 1 * TILEB + boff[np] + klo); \
            _Pragma("unroll")                                                    \
            for (int mt = 0; mt < 4; mt++)                                       \
                _Pragma("unroll")                                                \
                for (int nt = 0; nt < 4; nt++)                                   \
                    mma16816(d[mt][nt], ah[mt], &bf[nt >> 1][(nt & 1) * 2]);     \
        }                                                                        \
    } while (0)

// 2-term MMA over one 128-k chunk, explicit slots: A single, B hi/lo (fused GEMM3)
#define MMA_STAGE_SB3(sA, sBh, sBl)                                              \
    do {                                                                         \
        _Pragma("unroll")                                                        \
        for (int ks = 0; ks < 8; ks++) {                                         \
            const uint32_t klo = ks * 32;                                        \
            uint32_t af[4][4], bh[2][4];                                         \
            _Pragma("unroll")                                                    \
            for (int mt = 0; mt < 4; mt++) ld4(af[mt], (sA) + aoff[mt] + klo);   \
            _Pragma("unroll")                                                    \
            for (int np = 0; np < 2; np++) ld4(bh[np], (sBh) + boff[np] + klo);  \
            _Pragma("unroll")                                                    \
            for (int mt = 0; mt < 4; mt++)                                       \
                _Pragma("unroll")                                                \
                for (int nt = 0; nt < 4; nt++)                                   \
                    mma16816(d[mt][nt], af[mt], &bh[nt >> 1][(nt & 1) * 2]);     \
            {                                                                    \
                uint32_t bl[2][4];                                               \
                _Pragma("unroll")                                                \
                for (int np = 0; np < 2; np++) ld4(bl[np], (sBl) + boff[np] + klo); \
                _Pragma("unroll")                                                \
                for (int mt = 0; mt < 4; mt++)                                   \
                    _Pragma("unroll")                                            \
                    for (int nt = 0; nt < 4; nt++)                               \
                        mma16816(d[mt][nt], af[mt], &bl[nt >> 1][(nt & 1) * 2]); \
            }                                                                    \
        }                                                                        \
    } while (0)

// fp32 LDG of a 128x64 half-chunk into registers (8 x float4 per thread)
__device__ __forceinline__ void ldgF(float4* br, const float* pB, int K, int k0) {
    const int t = threadIdx.x;
#pragma unroll
    for (int p = 0; p < 8; p++) {
        int idx = p * 256 + t;
        int row = idx >> 4, f4 = idx & 15;
        br[p] = *(const float4*)(pB + (size_t)row * K + k0 + f4 * 4);
    }
}
// fp16-round STS of a 64-col half into one tile slot at byte offset kb
__device__ __forceinline__ void cvt_sts1(const float4* br, uint32_t slot, uint32_t kb) {
    const int t = threadIdx.x;
#pragma unroll
    for (int p = 0; p < 8; p++) {
        int idx = p * 256 + t;
        int row = idx >> 4, f4 = idx & 15;
        float4 v = br[p];
        __half2 h01 = __floats2half2_rn(v.x, v.y);
        __half2 h23 = __floats2half2_rn(v.z, v.w);
        uint32_t off = (uint32_t)(row * RSTR + kb + f4 * 8);
        asm volatile("st.shared.v2.b32 [%0], {%1,%2};"
            :: "r"(slot + off), "r"(*(uint32_t*)&h01), "r"(*(uint32_t*)&h23));
    }
}

// ---------------------------------------------------------------------------
// GEMM1 (1-term): hs1^T[j, c-tile] = w0_fp16[j,:] . x_fp16[b, c,:] + fused q/k partials
// ---------------------------------------------------------------------------
__global__ __launch_bounds__(256, 1) void mma_gemm_x(
    const __half* __restrict__ Ah,
    const float* __restrict__ Bf, long b_bstr,
    int K,
    const float* __restrict__ bias,
    __half* __restrict__ oh,
    long o_bstr, int o_rstr)
{
    extern __shared__ char dsm[];
    const uint32_t sb = smem_u32(dsm);

    const int tid = threadIdx.x;
    const int wid = tid >> 5, lane = tid & 31;
    const int bz = blockIdx.z;
    const int Boff = blockIdx.x * 128;
    const float* pBf = Bf + (size_t)bz * b_bstr + (size_t)Boff * K;

    const int m_base = (wid >> 2) * 64;
    const int n_base = (wid & 3) * 32;
    const int quad = lane >> 3, id8 = lane & 7;

    uint32_t aoff[4], boff[2];
#pragma unroll
    for (int mt = 0; mt < 4; mt++)
        aoff[mt] = (uint32_t)((m_base + mt * 16 + (quad & 1) * 8 + id8) * RSTR + ((quad >> 1) * 8) * 2);
#pragma unroll
    for (int np = 0; np < 2; np++)
        boff[np] = (uint32_t)((n_base + np * 16 + (quad >> 1) * 8 + id8) * RSTR + ((quad & 1) * 8) * 2);

    float d[4][4][4];
#pragma unroll
    for (int mt = 0; mt < 4; mt++)
#pragma unroll
        for (int nt = 0; nt < 4; nt++)
#pragma unroll
            for (int k = 0; k < 4; k++) d[mt][nt][k] = 0.f;

    const int nk = K / BK;   // 16
    float4 br0[8], br1[8];

    // prologue: chunk0 + chunk1 staged
    ldgF(br0, pBf, K, 0);
    ldgF(br1, pBf, K, 64);
    cvt_sts1(br0, sb + 1 * TILEB, 0);
    cvt_sts1(br1, sb + 1 * TILEB, 128);
    load_tile(sb + 0 * TILEB, Ah, K, 0);
    CP_COMMIT();
    ldgF(br0, pBf, K, BK);
    ldgF(br1, pBf, K, BK + 64);
    cvt_sts1(br0, sb + STG2 + 1 * TILEB, 0);
    cvt_sts1(br1, sb + STG2 + 1 * TILEB, 128);
    load_tile(sb + STG2 + 0 * TILEB, Ah, K, BK);
    CP_COMMIT();
    CP_WAIT1();
    __syncthreads();

    for (int i = 0; i < nk; i++) {
        const uint32_t st = sb + (i & 1) * STG2;
        if (i + 2 < nk) {
            ldgF(br0, pBf, K, (i + 2) * BK);
            ldgF(br1, pBf, K, (i + 2) * BK + 64);
        }

        MMA_STAGE_1T(st);

        __syncthreads();
        if (i + 2 < nk) {
            cvt_sts1(br0, st + 1 * TILEB, 0);
            cvt_sts1(br1, st + 1 * TILEB, 128);
            load_tile(st + 0 * TILEB, Ah, K, (i + 2) * BK);
            CP_COMMIT();
        }
        if (i + 1 < nk) {
            if (i + 2 < nk) CP_WAIT1(); else CP_WAIT0();
            __syncthreads();
        }
    }

    // epilogue: write fp16 hs1^T AND fused q/k partial sums
    __syncthreads();
    float* red = (float*)dsm;
    const int g = lane >> 2, t2 = (lane & 3) * 2;
    const int nw = wid & 3;
#pragma unroll
    for (int mt = 0; mt < 4; mt++) {
        const int r0 = m_base + mt * 16 + g;
        const int r1 = r0 + 8;
        const float bv0 = bias[r0];
        const float bv1 = bias[r1];
        const size_t base0 = (size_t)bz * o_bstr + (size_t)r0 * o_rstr + Boff;
        const size_t base1 = (size_t)bz * o_bstr + (size_t)r1 * o_rstr + Boff;
        float pq0 = 0.f, pk0 = 0.f, pq1 = 0.f, pk1 = 0.f;
#pragma unroll
        for (int nt = 0; nt < 4; nt++) {
            const int col = n_base + nt * 8 + t2;
            float v00 = d[mt][nt][0] + bv0, v01 = d[mt][nt][1] + bv0;
            float v10 = d[mt][nt][2] + bv1, v11 = d[mt][nt][3] + bv1;
            *(__half2*)(oh + base0 + col) = __floats2half2_rn(v00, v01);
            *(__half2*)(oh + base1 + col) = __floats2half2_rn(v10, v11);
            float wqa = g_wqm[Boff + col], wqb = g_wqm[Boff + col + 1];
            float wka = g_wkm[Boff + col], wkb = g_wkm[Boff + col + 1];
            pq0 = fmaf(v00, wqa, fmaf(v01, wqb, pq0));
            pk0 = fmaf(v00, wka, fmaf(v01, wkb, pk0));
            pq1 = fmaf(v10, wqa, fmaf(v11, wqb, pq1));
            pk1 = fmaf(v10, wka, fmaf(v11, wkb, pk1));
        }
#pragma unroll
        for (int o = 2; o > 0; o >>= 1) {
            pq0 += __shfl_down_sync(0xffffffffu, pq0, o, 4);
            pk0 += __shfl_down_sync(0xffffffffu, pk0, o, 4);
            pq1 += __shfl_down_sync(0xffffffffu, pq1, o, 4);
            pk1 += __shfl_down_sync(0xffffffffu, pk1, o, 4);
        }
        if ((lane & 3) == 0) {
            red[0 * 512 + nw * 128 + r0] = pq0; red[0 * 512 + nw * 128 + r1] = pq1;
            red[1 * 512 + nw * 128 + r0] = pk0; red[1 * 512 + nw * 128 + r1] = pk1;
        }
    }
    __syncthreads();
    if (tid < 128) {
        float q = red[tid] + red[128 + tid] + red[256 + tid] + red[384 + tid];
        float k = red[512 + tid] + red[640 + tid] + red[768 + tid] + red[896 + tid];
        const size_t o = ((size_t)bz * NCT + blockIdx.x) * NJ + tid;
        g_qp[o] = q;
        g_kp[o] = k;
    }
}

// ---------------------------------------------------------------------------
// GEMM2 (1-term) + fused A1 build + fused GEMM3 + fused BN-stat/pool
// smem = 4 tiles. Mainloop stages {0,1},{2,3}.
// Epilogue: hs2 -> tile0, q1/k1 -> tile3 scratch, A1 hi/lo -> tiles 1,2.
// ---------------------------------------------------------------------------
__global__ __launch_bounds__(256, 1) void mma_gemm2f(
    const float* __restrict__ C1f,
    const __half* __restrict__ H1, long h1_bstr,
    int K,
    const float* __restrict__ bias,
    const float* __restrict__ adj, const float* __restrict__ alpha,
    const float* __restrict__ w1f,
    float* __restrict__ sbc, float* __restrict__ ssbc, float* __restrict__ dotb)
{
    extern __shared__ char dsm[];
    const uint32_t sb = smem_u32(dsm);

    const int tid = threadIdx.x;
    const int wid = tid >> 5, lane = tid & 31;
    const int bz = blockIdx.z;
    const int Aoff = blockIdx.x * 128;

    const float* pAf = C1f + (size_t)Aoff * K;
    const __half* p2 = H1 + (size_t)bz * h1_bstr;

    const int m_base = (wid >> 2) * 64;
    const int n_base = (wid & 3) * 32;
    const int quad = lane >> 3, id8 = lane & 7;

    uint32_t aoff[4], boff[2];
#pragma unroll
    for (int mt = 0; mt < 4; mt++)
        aoff[mt] = (uint32_t)((m_base + mt * 16 + (quad & 1) * 8 + id8) * RSTR + ((quad >> 1) * 8) * 2);
#pragma unroll
    for (int np = 0; np < 2; np++)
        boff[np] = (uint32_t)((n_base + np * 16 + (quad >> 1) * 8 + id8) * RSTR + ((quad & 1) * 8) * 2);

    float d[4][4][4];
#pragma unroll
    for (int mt = 0; mt < 4; mt++)
#pragma unroll
        for (int nt = 0; nt < 4; nt++)
#pragma unroll
            for (int k = 0; k < 4; k++) d[mt][nt][k] = 0.f;

    const int nk = K / BK;   // 12
    float4 br0[8], br1[8];

    // prologue: A = c1 (ldg+round into tile0), B = h1 (cp.async into tile1)
    ldgF(br0, pAf, K, 0);
    ldgF(br1, pAf, K, 64);
    cvt_sts1(br0, sb + 0 * TILEB, 0);
    cvt_sts1(br1, sb + 0 * TILEB, 128);
    load_tile(sb + 1 * TILEB, p2, K, 0);
    CP_COMMIT();
    ldgF(br0, pAf, K, BK);
    ldgF(br1, pAf, K, BK + 64);
    cvt_sts1(br0, sb + STG2 + 0 * TILEB, 0);
    cvt_sts1(br1, sb + STG2 + 0 * TILEB, 128);
    load_tile(sb + STG2 + 1 * TILEB, p2, K, BK);
    CP_COMMIT();
    CP_WAIT1();
    __syncthreads();

    for (int i = 0; i < nk; i++) {
        const uint32_t st = sb + (i & 1) * STG2;
        if (i + 2 < nk) {
            ldgF(br0, pAf, K, (i + 2) * BK);
            ldgF(br1, pAf, K, (i + 2) * BK + 64);
        }

        MMA_STAGE_1T(st);

        __syncthreads();
        if (i + 2 < nk) {
            cvt_sts1(br0, st + 0 * TILEB, 0);
            cvt_sts1(br1, st + 0 * TILEB, 128);
            load_tile(st + 1 * TILEB, p2, K, (i + 2) * BK);
            CP_COMMIT();
        }
        if (i + 1 < nk) {
            if (i + 2 < nk) CP_WAIT1(); else CP_WAIT0();
            __syncthreads();
        }
    }
    // all MMAs done — all 4 tiles free

    // --- phase 1: hs2 (+bias, fp16) -> tile0; q1/k1 reduce -> tile3 scratch ---
    const int g = lane >> 2, t2 = (lane & 3) * 2;
#pragma unroll
    for (int mt = 0; mt < 4; mt++) {
        const int r0 = m_base + mt * 16 + g;
        const int r1 = r0 + 8;
        const float bv0 = bias[Aoff + r0];
        const float bv1 = bias[Aoff + r1];
#pragma unroll
        for (int nt = 0; nt < 4; nt++) {
            const int col = n_base + nt * 8 + t2;
            __half2 v0 = __floats2half2_rn(d[mt][nt][0] + bv0, d[mt][nt][1] + bv0);
            __half2 v1 = __floats2half2_rn(d[mt][nt][2] + bv1, d[mt][nt][3] + bv1);
            asm volatile("st.shared.b32 [%0], %1;"
                :: "r"(sb + (uint32_t)r0 * RSTR + (uint32_t)col * 2), "r"(*(uint32_t*)&v0));
            asm volatile("st.shared.b32 [%0], %1;"
                :: "r"(sb + (uint32_t)r1 * RSTR + (uint32_t)col * 2), "r"(*(uint32_t*)&v1));
        }
    }
    float* qks = (float*)(dsm + 3 * TILEB);   // [q1 0..127][k1 128..255]
    if (tid < 128) {
        float q = g_bqkm[0], k = g_bqkm[1];
#pragma unroll
        for (int t = 0; t < NCT; t++) {
            q += g_qp[((size_t)bz * NCT + t) * NJ + tid];
            k += g_kp[((size_t)bz * NCT + t) * NJ + tid];
        }
        qks[tid] = q; qks[128 + tid] = k;
    }
    __syncthreads();

    // --- phase 2: A1^T[k][j] hi/lo -> tiles 1,2 ---
    {
        const float a = alpha[0];
#pragma unroll
        for (int u = 0; u < 32; u++) {
            const int idx2 = u * 512 + tid * 2;        // even, < 16384
            const int k = idx2 >> 7, j = idx2 & 127;
            float q0 = qks[j], q1 = qks[j + 1];
            float kk = qks[128 + k];
            float v0 = adj[j * NJ + k] + tanhf(q0 - kk) * a;
            float v1 = adj[(j + 1) * NJ + k] + tanhf(q1 - kk) * a;
            __half2 h = __floats2half2_rn(v0, v1);
            float2 hf = __half22float2(h);
            __half2 l = __floats2half2_rn(v0 - hf.x, v1 - hf.y);
            const uint32_t off = (uint32_t)k * RSTR + (uint32_t)j * 2;
            asm volatile("st.shared.b32 [%0], %1;"
                :: "r"(sb + 1 * TILEB + off), "r"(*(uint32_t*)&h));
            asm volatile("st.shared.b32 [%0], %1;"
                :: "r"(sb + 2 * TILEB + off), "r"(*(uint32_t*)&l));
        }
    }
    __syncthreads();

#pragma unroll
    for (int mt = 0; mt < 4; mt++)
#pragma unroll
        for (int nt = 0; nt < 4; nt++)
#pragma unroll
            for (int k = 0; k < 4; k++) d[mt][nt][k] = 0.f;

    MMA_STAGE_SB3(sb + 0 * TILEB, sb + 1 * TILEB, sb + 2 * TILEB);

    // --- fused BN-stat + pool epilogue ---
    __syncthreads();
    float* red = (float*)dsm;
    const int nw = wid & 3;
#pragma unroll
    for (int mt = 0; mt < 4; mt++) {
        float s0r = 0, ss0 = 0, dt0 = 0, s1r = 0, ss1 = 0, dt1 = 0;
#pragma unroll
        for (int nt = 0; nt < 4; nt++) {
            const int col = n_base + nt * 8 + t2;
            float wa = __ldg(w1f + col), wb = __ldg(w1f + col + 1);
            float v00 = d[mt][nt][0], v01 = d[mt][nt][1];
            float v10 = d[mt][nt][2], v11 = d[mt][nt][3];
            s0r += v00 + v01;  ss0 = fmaf(v00, v00, fmaf(v01, v01, ss0));
            dt0 = fmaf(v00, wa, fmaf(v01, wb, dt0));
            s1r += v10 + v11;  ss1 = fmaf(v10, v10, fmaf(v11, v11, ss1));
            dt1 = fmaf(v10, wa, fmaf(v11, wb, dt1));
        }
#pragma unroll
        for (int o = 2; o > 0; o >>= 1) {
            s0r += __shfl_down_sync(0xffffffffu, s0r, o, 4);
            ss0 += __shfl_down_sync(0xffffffffu, ss0, o, 4);
            dt0 += __shfl_down_sync(0xffffffffu, dt0, o, 4);
            s1r += __shfl_down_sync(0xffffffffu, s1r, o, 4);
            ss1 += __shfl_down_sync(0xffffffffu, ss1, o, 4);
            dt1 += __shfl_down_sync(0xffffffffu, dt1, o, 4);
        }
        if ((lane & 3) == 0) {
            const int r0 = m_base + mt * 16 + g, r1 = r0 + 8;
            red[0 * 512 + nw * 128 + r0] = s0r; red[0 * 512 + nw * 128 + r1] = s1r;
            red[1 * 512 + nw * 128 + r0] = ss0; red[1 * 512 + nw * 128 + r1] = ss1;
            red[2 * 512 + nw * 128 + r0] = dt0; red[2 * 512 + nw * 128 + r1] = dt1;
        }
    }
    __syncthreads();
    if (tid < 128) {
        float s  = red[tid] + red[128 + tid] + red[256 + tid] + red[384 + tid];
        float ss = red[512 + tid] + red[640 + tid] + red[768 + tid] + red[896 + tid];
        float dt = red[1024 + tid] + red[1152 + tid] + red[1280 + tid] + red[1408 + tid];
        const size_t o = (size_t)bz * PS + Aoff + tid;
        sbc[o] = s; ssbc[o] = ss; dotb[o] = dt;
    }
}

// ---------------------------------------------------------------------------
// small kernels
// ---------------------------------------------------------------------------
// hs4: block (32 b-lanes, 8 c), grid PS/8 = 192
__global__ void k_hs4(const float* __restrict__ gamma, const float* __restrict__ beta,
                      const float* __restrict__ w1, const float* __restrict__ b1) {
    __shared__ float sws;
    const int tid = threadIdx.y * 32 + threadIdx.x;
    if (tid < 32) {
        float sw = 0.f;
#pragma unroll
        for (int j = tid; j < NJ; j += 32) sw += w1[j];
#pragma unroll
        for (int o = 16; o > 0; o >>= 1) sw += __shfl_down_sync(0xffffffffu, sw, o);
        if (tid == 0) sws = sw;
    }
    __syncthreads();
    const float sw = sws;
    const int c = blockIdx.x * 8 + threadIdx.y;
    const int b = threadIdx.x;
    const size_t o = (size_t)b * PS + c;
    float st  = g_sbc[o];
    float sst = g_ssbc[o];
#pragma unroll
    for (int u = 16; u > 0; u >>= 1) {
        st  += __shfl_down_sync(0xffffffffu, st, u);
        sst += __shfl_down_sync(0xffffffffu, sst, u);
    }
    st  = __shfl_sync(0xffffffffu, st, 0);
    sst = __shfl_sync(0xffffffffu, sst, 0);
    const float inv = 1.0f / (BB * NJ);
    float mean = st * inv;
    float var = sst * inv - mean * mean;
    float rstd = rsqrtf(var + 1e-5f);
    float ga = gamma[c] * rstd;
    float be = beta[c] * sw + b1[0];
    float msw = mean * sw;
    g_hs4[b * PS + c] = ga * (g_dotb[o] - msw) + be;
}

__global__ void k_cls(const float* __restrict__ wcls, const float* __restrict__ bcls,
                      float* __restrict__ out) {
    __shared__ __align__(16) float sh[PS];
    const int b = blockIdx.x;
    for (int i = threadIdx.x; i < PS; i += blockDim.x) sh[i] = g_hs4[b * PS + i];
    __syncthreads();
    const int n = threadIdx.x;
    if (n < NC) {
        float acc = bcls[n];
        const float4* w4 = (const float4*)(wcls + (size_t)n * PS);
        const float4* s4 = (const float4*)sh;
        for (int c = 0; c < PS / 4; c++) {
            float4 w = w4[c], s = s4[c];
            acc = fmaf(s.x, w.x, acc);
            acc = fmaf(s.y, w.y, acc);
            acc = fmaf(s.z, w.z, acc);
            acc = fmaf(s.w, w.w, acc);
        }
        out[b * NC + n] = acc;
    }
}

// ---------------------------------------------------------------------------
// launch
// ---------------------------------------------------------------------------
extern "C" void kernel_launch(void* const* d_in, const int* in_sizes, int n_in,
                              void* d_out, int out_size) {
    (void)in_sizes; (void)n_in; (void)out_size;
    const float* x       = (const float*)d_in[0];
    const float* w_pool0 = (const float*)d_in[1];
    const float* b_pool0 = (const float*)d_in[2];
    const float* adj1    = (const float*)d_in[3];
    const float* w_q     = (const float*)d_in[4];
    const float* b_q     = (const float*)d_in[5];
    const float* w_k     = (const float*)d_in[6];
    const float* b_k     = (const float*)d_in[7];
    const float* alpha   = (const float*)d_in[8];
    const float* w_c1    = (const float*)d_in[9];
    const float* b_c1    = (const float*)d_in[10];
    const float* gamma   = (const float*)d_in[11];
    const float* beta    = (const float*)d_in[12];
    const float* w_pool1 = (const float*)d_in[13];
    const float* b_pool1 = (const float*)d_in[14];
    const float* w_cls   = (const float*)d_in[15];
    const float* b_cls   = (const float*)d_in[16];
    float* out = (float*)d_out;

    __half *w0h, *h1;
    float *sbc, *ssbc, *dotb;
    cudaGetSymbolAddress((void**)&w0h,  g_w0h);
    cudaGetSymbolAddress((void**)&h1,   g_h1);
    cudaGetSymbolAddress((void**)&sbc,  g_sbc);
    cudaGetSymbolAddress((void**)&ssbc, g_ssbc);
    cudaGetSymbolAddress((void**)&dotb, g_dotb);

    const int smem_bytes = 2 * STG2;   // 139264 (4 tiles)
    cudaFuncSetAttribute(mma_gemm2f, cudaFuncAttributeMaxDynamicSharedMemorySize, smem_bytes);
    cudaFuncSetAttribute(mma_gemm_x, cudaFuncAttributeMaxDynamicSharedMemorySize, smem_bytes);

    // combined prep (w0 round + wq/wk means + bias means)
    k_prep<<<306, 256>>>(w_pool0, w_q, w_k, b_q, b_k);

    // GEMM1 (1-term, BK=128) + fused q/k partials
    mma_gemm_x<<<dim3(NCT, 1, BB), 256, smem_bytes>>>(
        w0h,
        x, (long)PS * TNS,
        TNS, b_pool0,
        h1, (long)NJ * PS, PS);

    // GEMM2 (1-term, inline c1 round) + fused A1 build + GEMM3 + BN-stat/pool
    mma_gemm2f<<<dim3(NCT, 1, BB), 256, smem_bytes>>>(
        w_c1,
        h1, (long)NJ * PS,
        PS, b_c1,
        adj1, alpha,
        w_pool1, sbc, ssbc, dotb);

    k_hs4<<<PS / 8, dim3(32, 8)>>>(gamma, beta, w_pool1, b_pool1);
    k_cls<<<BB, 256>>>(w_cls, b_cls, out);
}